// round 9
// baseline (speedup 1.0000x reference)
#include <cuda_runtime.h>
#include <cstdint>

// LocalPatternExtractor: reference forward output is identically zero.
//
// Proof (forward values; stop_gradient is identity in the forward pass):
//   - quantize_pot_ste clips round(mem*128) to [-128, 127]; quantized membrane
//     potential <= 127/128 = 0.9921875 < THRESHOLD (1.0) -> spike (mem>=1.0)
//     is always false -> acc = 0 -> out = zeros, reg_loss = 0.
//   (Confirmed: rel_err = 0.0 across rounds 2-8.)
//
// Store-path ladder so far (82 MB zero-fill):
//   STG.128 grid-stride:      ~4.0 TB/s (21.0us kernel)
//   STG.256 (st.global.v4.f64): ~5.7 TB/s (14.4us kernel)
//   driver memset:            ~7 TB/s  (14.8us harness)  <- best
// Nothing saturated in ncu at any point -> per-lane store pipeline is the
// limiter. This round: TMA bulk stores (cp.async.bulk SMEM->GMEM) bypass the
// per-lane path entirely; B300 TMA chip throughput = same ~6300 B/cyc LTS cap
// as loads (~12 TB/s @ NAT) if the write direction matches.

static constexpr int SMEM_BYTES = 32768;          // 32 KB staging buffer
static constexpr int BLOCK = 128;

__global__ void __launch_bounds__(BLOCK)
zero_fill_tma(char* __restrict__ out, size_t total_units /* 16B units */,
              float* __restrict__ tail, int n_tail) {
    __shared__ __align__(1024) char buf[SMEM_BYTES];

    // Zero the staging buffer (one-time, 16 int4 stores per thread).
    int4* b4 = (int4*)buf;
    int4 z4 = make_int4(0, 0, 0, 0);
    #pragma unroll
    for (int i = threadIdx.x; i < SMEM_BYTES / 16; i += BLOCK) {
        b4[i] = z4;
    }
    __syncthreads();
    // Order generic-proxy SMEM writes before async-proxy (TMA) reads.
    asm volatile("fence.proxy.async.shared::cta;" ::: "memory");

    if (threadIdx.x == 0) {
        uint32_t s;
        asm("{ .reg .u64 t; cvta.to.shared.u64 t, %1; cvt.u32.u64 %0, t; }"
            : "=r"(s) : "l"((void*)buf));

        // Contiguous slice per CTA.
        size_t per = (total_units + gridDim.x - 1) / gridDim.x;
        size_t begin = (size_t)blockIdx.x * per;
        size_t end = begin + per;
        if (end > total_units) end = total_units;

        size_t u = begin;
        while (u < end) {
            size_t nu = end - u;
            if (nu > (size_t)(SMEM_BYTES / 16)) nu = SMEM_BYTES / 16;
            uint32_t bytes = (uint32_t)(nu * 16);
            asm volatile(
                "cp.async.bulk.global.shared::cta.bulk_group [%0], [%1], %2;"
                :: "l"(out + u * 16), "r"(s), "r"(bytes) : "memory");
            u += nu;
        }
        asm volatile("cp.async.bulk.commit_group;" ::: "memory");
        asm volatile("cp.async.bulk.wait_group 0;" ::: "memory");
    }

    // 4-byte tail (81,920,004 % 16), handled by block 0 lanes 32..
    if (blockIdx.x == 0 && threadIdx.x >= 32 && threadIdx.x < 32 + n_tail) {
        tail[threadIdx.x - 32] = 0.f;
    }
}

extern "C" void kernel_launch(void* const* d_in, const int* in_sizes, int n_in,
                              void* d_out, int out_size) {
    (void)d_in; (void)in_sizes; (void)n_in;

    size_t n_bytes = (size_t)out_size * sizeof(float);   // 81,920,004
    size_t total_units = n_bytes / 16;                   // 5,120,000 x 16B
    size_t covered = total_units * 16;
    int n_tail = (int)((n_bytes - covered) / 4);         // 1 float
    float* tail_ptr = (float*)((char*)d_out + covered);

    // 592 CTAs = 4/SM x 148 SMs (4 x 32KB = 128KB SMEM/SM), each CTA covers
    // ~138KB of output via ~4-5 bulk 32KB stores.
    zero_fill_tma<<<592, BLOCK>>>((char*)d_out, total_units, tail_ptr, n_tail);
}

// round 10
// speedup vs baseline: 1.0057x; 1.0057x over previous
#include <cuda_runtime.h>
#include <cstdint>

// LocalPatternExtractor: reference forward output is identically zero.
//   quantize clips mem to <= 127/128 < THRESHOLD=1.0 -> spike always 0 ->
//   out = zeros(16,256,5000), reg_loss = 0. (rel_err = 0.0, rounds 2-9.)
//
// Store-path ladder (82 MB zero-fill, kernel-level):
//   STG.128:  ~4.0 TB/s   STG.256: ~5.7 TB/s   TMA bulk: ~5.8 TB/s
//   memset:   ~6.5-7 TB/s (14.8us harness, best)
// STG.256 and TMA hit the SAME ~5.8 TB/s with L2 at only ~49% and totally
// different issue paths (LSU per-lane vs TMA engine, occ 6.8% / issue 1.9%
// for TMA). Theory: the caps are per-path, not a shared L2 write cap ->
// run BOTH paths concurrently on disjoint halves and they should add.

static constexpr int SMEM_BYTES = 32768;
static constexpr int BLOCK = 256;
static constexpr int GRID = 592;                     // 4 CTAs/SM x 148 SMs
static constexpr int STG_THREADS_PER_CTA = BLOCK - 32;

__global__ void __launch_bounds__(BLOCK)
zero_fill_hybrid(char* __restrict__ out,
                 size_t tma_units,     // 16B units in TMA region [0, ...)
                 size_t stg_chunks,    // 32B chunks in STG region
                 size_t stg_base,      // byte offset of STG region
                 float* __restrict__ tail, int n_tail) {
    __shared__ __align__(1024) char buf[SMEM_BYTES];

    // Zero staging buffer.
    int4* b4 = (int4*)buf;
    int4 z4 = make_int4(0, 0, 0, 0);
    #pragma unroll
    for (int i = threadIdx.x; i < SMEM_BYTES / 16; i += BLOCK) {
        b4[i] = z4;
    }
    __syncthreads();
    asm volatile("fence.proxy.async.shared::cta;" ::: "memory");

    if (threadIdx.x == 0) {
        // ---- TMA path: this CTA's contiguous slice of the first region ----
        uint32_t s;
        asm("{ .reg .u64 t; cvta.to.shared.u64 t, %1; cvt.u32.u64 %0, t; }"
            : "=r"(s) : "l"((void*)buf));

        size_t per = (tma_units + GRID - 1) / GRID;
        size_t begin = (size_t)blockIdx.x * per;
        size_t end = begin + per;
        if (end > tma_units) end = tma_units;

        size_t u = begin;
        while (u < end) {
            size_t nu = end - u;
            if (nu > (size_t)(SMEM_BYTES / 16)) nu = SMEM_BYTES / 16;
            asm volatile(
                "cp.async.bulk.global.shared::cta.bulk_group [%0], [%1], %2;"
                :: "l"(out + u * 16), "r"(s), "r"((uint32_t)(nu * 16))
                : "memory");
            u += nu;
        }
        asm volatile("cp.async.bulk.commit_group;" ::: "memory");
        asm volatile("cp.async.bulk.wait_group 0;" ::: "memory");
    } else if (threadIdx.x >= 32) {
        // ---- STG.256 path: grid-stride over the second region ----
        double* stg = (double*)(out + stg_base);
        const size_t nthreads = (size_t)GRID * STG_THREADS_PER_CTA;
        size_t i = (size_t)blockIdx.x * STG_THREADS_PER_CTA
                 + (threadIdx.x - 32);
        const double z = 0.0;
        for (; i < stg_chunks; i += nthreads) {
            double* p = stg + i * 4;
            asm volatile("st.global.v4.f64 [%0], {%1, %1, %1, %1};"
                         :: "l"(p), "d"(z) : "memory");
        }
    }

    // 4-byte tail, block 0 lanes 1..n_tail of warp 0.
    if (blockIdx.x == 0 && threadIdx.x >= 1 && threadIdx.x <= (unsigned)n_tail) {
        tail[threadIdx.x - 1] = 0.f;
    }
}

extern "C" void kernel_launch(void* const* d_in, const int* in_sizes, int n_in,
                              void* d_out, int out_size) {
    (void)d_in; (void)in_sizes; (void)n_in;

    size_t n_bytes = (size_t)out_size * sizeof(float);   // 81,920,004
    size_t vec_bytes = n_bytes & ~(size_t)31;            // 32B-aligned body
    int n_tail = (int)((n_bytes - vec_bytes) / 4);       // 1 float
    float* tail_ptr = (float*)((char*)d_out + vec_bytes);

    // Split: 45% TMA / 55% STG, both aligned.
    size_t tma_bytes = (size_t)(vec_bytes * 0.45);
    tma_bytes &= ~(size_t)32767;                         // 32KB-align for clean chunks
    size_t tma_units = tma_bytes / 16;
    size_t stg_chunks = (vec_bytes - tma_bytes) / 32;

    zero_fill_hybrid<<<GRID, BLOCK>>>((char*)d_out, tma_units, stg_chunks,
                                      tma_bytes, tail_ptr, n_tail);
}